// round 3
// baseline (speedup 1.0000x reference)
#include <cuda_runtime.h>
#include <math.h>
#include <stdint.h>

#define BB 4
#define TT 2048
#define CC 1024
#define HH 64
#define NROWS (BB * TT)   // 8192

__device__ float g_q[NROWS * HH];
__device__ float g_k[NROWS * HH];
__device__ float g_v[NROWS * HH];

typedef unsigned long long ull;

// ---------------- f32x2 helpers ----------------
__device__ __forceinline__ void ffma2(ull& d, ull a, ull b) {
    asm("fma.rn.f32x2 %0, %1, %2, %0;" : "+l"(d) : "l"(a), "l"(b));
}
__device__ __forceinline__ void fmul2(ull& d, ull a) {
    asm("mul.rn.f32x2 %0, %0, %1;" : "+l"(d) : "l"(a));
}
__device__ __forceinline__ ull pack2(float lo, float hi) {
    ull r; asm("mov.b64 %0, {%1, %2};" : "=l"(r) : "f"(lo), "f"(hi)); return r;
}
__device__ __forceinline__ void unpack2(ull v, float& a, float& b) {
    asm("mov.b64 {%0, %1}, %2;" : "=f"(a), "=f"(b) : "l"(v));
}
__device__ __forceinline__ void lds_2x64(ull& a, ull& b, const void* p) {
    uint32_t sa = (uint32_t)__cvta_generic_to_shared(p);
    asm volatile("ld.shared.v2.u64 {%0, %1}, [%2];" : "=l"(a), "=l"(b) : "r"(sa));
}
__device__ __forceinline__ void cp_async16(void* smem_dst, const void* gptr) {
    uint32_t sa = (uint32_t)__cvta_generic_to_shared(smem_dst);
    asm volatile("cp.async.cg.shared.global [%0], [%1], 16;" :: "r"(sa), "l"(gptr));
}
#define CP_COMMIT() asm volatile("cp.async.commit_group;")
#define CP_WAIT(n)  asm volatile("cp.async.wait_group %0;" :: "n"(n))

// ---------------------------------------------------------------------------
// Kernel 1: QKV projection, f32x2 (FFMA2) 8x8 register tile.
// Block 128 threads -> tile 128(m) x 64(n), BK=16.
// As[m][k] (k-minor), Bs[n][k] (k-minor, transposed on load), XOR swizzled.
// grid = (64, 3)
// ---------------------------------------------------------------------------
__global__ __launch_bounds__(128, 2) void proj_kernel(
    const float* __restrict__ x,
    const float* __restrict__ Wq,
    const float* __restrict__ Wk,
    const float* __restrict__ Wv)
{
    const float* W = (blockIdx.y == 0) ? Wq : (blockIdx.y == 1) ? Wk : Wv;
    float* out     = (blockIdx.y == 0) ? g_q : (blockIdx.y == 1) ? g_k : g_v;

    __shared__ float As[2][128 * 16];   // [m][k], row = 64B, swizzle key (m>>3)&3
    __shared__ float Bs[2][64 * 16];    // [n][k], swizzle key (n>>3)&3

    const int tid  = threadIdx.x;
    const int tm   = tid >> 3;          // 0..15
    const int tn   = tid & 7;           // 0..7
    const int row0 = blockIdx.x * 128;

    // B load lanes: thread covers k-row kk, 8 n's starting at n0
    const int kk = tid >> 3;            // 0..15
    const int n0 = (tid & 7) * 8;

    ull acc[8][8] = {};

    // prologue: A tile 0 via cp.async, B tile 0 via LDG regs
    {
        const float* xr = &x[(row0 + tid) * CC + 0];
#pragma unroll
        for (int c = 0; c < 4; c++)
            cp_async16(&As[0][tid * 16 + ((c ^ (tm & 3)) << 2)], xr + c * 4);
        CP_COMMIT();
    }
    float4 bv0 = *(const float4*)&W[kk * HH + n0];
    float4 bv1 = *(const float4*)&W[kk * HH + n0 + 4];

    for (int kt = 0; kt < 64; kt++) {
        const int buf = kt & 1;
        // commit B regs -> smem (transpose)
        {
            float bvals[8] = {bv0.x, bv0.y, bv0.z, bv0.w, bv1.x, bv1.y, bv1.z, bv1.w};
#pragma unroll
            for (int e = 0; e < 8; e++) {
                const int n = n0 + e;
                Bs[buf][n * 16 + (((kk >> 2) ^ (tn & 3)) << 2) + (kk & 3)] = bvals[e];
            }
        }
        // issue next tile
        if (kt + 1 < 64) {
            const int nbuf = (kt + 1) & 1;
            const float* xr = &x[(row0 + tid) * CC + (kt + 1) * 16];
#pragma unroll
            for (int c = 0; c < 4; c++)
                cp_async16(&As[nbuf][tid * 16 + ((c ^ (tm & 3)) << 2)], xr + c * 4);
            CP_COMMIT();
            bv0 = *(const float4*)&W[((kt + 1) * 16 + kk) * HH + n0];
            bv1 = *(const float4*)&W[((kt + 1) * 16 + kk) * HH + n0 + 4];
            CP_WAIT(1);
        } else {
            CP_WAIT(0);
        }
        __syncthreads();

#pragma unroll
        for (int c4 = 0; c4 < 4; c4++) {
            ull a2[8][2], b2[8][2];
#pragma unroll
            for (int r = 0; r < 8; r++)
                lds_2x64(a2[r][0], a2[r][1],
                         &As[buf][(tm * 8 + r) * 16 + ((c4 ^ (tm & 3)) << 2)]);
#pragma unroll
            for (int c = 0; c < 8; c++)
                lds_2x64(b2[c][0], b2[c][1],
                         &Bs[buf][(tn * 8 + c) * 16 + ((c4 ^ (tn & 3)) << 2)]);
#pragma unroll
            for (int r = 0; r < 8; r++)
#pragma unroll
                for (int c = 0; c < 8; c++) {
                    ffma2(acc[r][c], a2[r][0], b2[c][0]);
                    ffma2(acc[r][c], a2[r][1], b2[c][1]);
                }
        }
        __syncthreads();
    }

    // epilogue: horizontal add of pairs, vectorized stores
#pragma unroll
    for (int r = 0; r < 8; r++) {
        float o[8];
#pragma unroll
        for (int c = 0; c < 8; c++) {
            float lo, hi; unpack2(acc[r][c], lo, hi);
            o[c] = lo + hi;
        }
        float* orow = &out[(row0 + tm * 8 + r) * HH + tn * 8];
        *(float4*)orow       = make_float4(o[0], o[1], o[2], o[3]);
        *(float4*)(orow + 4) = make_float4(o[4], o[5], o[6], o[7]);
    }
}

// ---------------------------------------------------------------------------
// Kernel 2: causal attention, f32x2 + cp.async double-buffered 128-key tiles.
// Block 256 threads (8 warps). Phases: q-tile p then 63-p (32 rows each).
// Warp w: rows 4w..4w+3. Lane l: score cols {l, l+32, l+64, l+96}; out dims
// {l, l+32} (rows packed in f32x2 pairs for PV).
// Dynamic smem 152KB: K[2][128][64] (swizzled), V[2][128][64], Q[32][64],
// Pt[8][128][4] (per-warp transposed P for broadcast reads).
// grid = (32, 4)
// ---------------------------------------------------------------------------
#define SM_K(buf)  (sm + (buf) * 8192)            // 2 x 8192 floats
#define SM_V(buf)  (sm + 16384 + (buf) * 8192)
#define SM_Q       (sm + 32768)                   // 2048 floats
#define SM_PT      (sm + 34816)                   // 4096 floats
#define ATTN_SMEM_BYTES ((34816 + 4096) * 4)      // 155648 = 152KB

__global__ __launch_bounds__(256, 1) void attn_kernel(float* __restrict__ out)
{
    extern __shared__ float sm[];

    const int b   = blockIdx.y;
    const int p   = blockIdx.x;
    const int tid = threadIdx.x;
    const int w   = tid >> 5;
    const int l   = tid & 31;

    const float* qb = g_q + b * TT * HH;
    const float* kb = g_k + b * TT * HH;
    const float* vb = g_v + b * TT * HH;
    float*       ob = out + b * TT * HH;

    float* ptw = SM_PT + (w << 9);   // [128][4]

    for (int phase = 0; phase < 2; phase++) {
        const int qt = phase ? (63 - p) : p;
        const int qs = qt * 32;

        __syncthreads();   // previous phase fully done with all smem

        // load Q tile (linear [row][c])
        for (int idx = tid; idx < 32 * 64; idx += 256)
            SM_Q[idx] = qb[qs * 64 + idx];

        float m[4], lsum[4];
        ull acc01[2] = {0ull, 0ull};   // rows {0,1} packed, dims l / l+32
        ull acc23[2] = {0ull, 0ull};   // rows {2,3} packed
#pragma unroll
        for (int i = 0; i < 4; i++) { m[i] = -INFINITY; lsum[i] = 0.f; }

        const int nkb = (qs + 32 + 127) >> 7;

        // prologue: issue K/V tile 0 into buf 0
        {
#pragma unroll
            for (int s = 0; s < 8; s++) {
                const int chunk = s * 256 + tid;          // 0..2047
                const int row = chunk >> 4, c4 = chunk & 15;
                cp_async16(SM_K(0) + row * 64 + ((c4 ^ (row & 7)) << 2),
                           &kb[row * 64 + c4 * 4]);
            }
#pragma unroll
            for (int s = 0; s < 8; s++) {
                const int chunk = s * 256 + tid;
                const int row = chunk >> 4, c4 = chunk & 15;
                cp_async16(SM_V(0) + row * 64 + c4 * 4,
                           &vb[row * 64 + c4 * 4]);
            }
            CP_COMMIT();
        }

        for (int t = 0; t < nkb; t++) {
            const int buf = t & 1;
            if (t + 1 < nkb) {
                const int nbuf = (t + 1) & 1;
                const float* kt_ = &kb[(t + 1) * 128 * 64];
                const float* vt_ = &vb[(t + 1) * 128 * 64];
#pragma unroll
                for (int s = 0; s < 8; s++) {
                    const int chunk = s * 256 + tid;
                    const int row = chunk >> 4, c4 = chunk & 15;
                    cp_async16(SM_K(nbuf) + row * 64 + ((c4 ^ (row & 7)) << 2),
                               kt_ + row * 64 + c4 * 4);
                }
#pragma unroll
                for (int s = 0; s < 8; s++) {
                    const int chunk = s * 256 + tid;
                    const int row = chunk >> 4, c4 = chunk & 15;
                    cp_async16(SM_V(nbuf) + row * 64 + c4 * 4,
                               vt_ + row * 64 + c4 * 4);
                }
                CP_COMMIT();
                CP_WAIT(1);
            } else {
                CP_WAIT(0);
            }
            __syncthreads();   // tile t (and Q) visible to all

            const float* Ks = SM_K(buf);
            const float* Vb = SM_V(buf);

            // ---- scores: s2[i][cc] accumulates {even-k, odd-k} pairs ----
            ull s2[4][4] = {};
#pragma unroll
            for (int c4 = 0; c4 < 16; c4++) {
                ull k2[4][2];
#pragma unroll
                for (int cc = 0; cc < 4; cc++)
                    lds_2x64(k2[cc][0], k2[cc][1],
                             &Ks[(l + 32 * cc) * 64 + ((c4 ^ (l & 7)) << 2)]);
                ull q2[2];
#pragma unroll
                for (int i = 0; i < 4; i++) {
                    lds_2x64(q2[0], q2[1], &SM_Q[((w << 2) + i) * 64 + c4 * 4]);
#pragma unroll
                    for (int cc = 0; cc < 4; cc++) {
                        ffma2(s2[i][cc], q2[0], k2[cc][0]);
                        ffma2(s2[i][cc], q2[1], k2[cc][1]);
                    }
                }
            }

            // ---- softmax (online), exact reference mask semantics ----
            float f[4];
#pragma unroll
            for (int i = 0; i < 4; i++) {
                const int rowg = qs + (w << 2) + i;
                float sc[4];
#pragma unroll
                for (int cc = 0; cc < 4; cc++) {
                    float lo, hi; unpack2(s2[i][cc], lo, hi);
                    float s = (lo + hi) * 0.125f;
                    const int col = t * 128 + l + 32 * cc;
                    if (col > rowg || s == 0.0f) s = -INFINITY;
                    sc[cc] = s;
                }
                float rmax = fmaxf(fmaxf(sc[0], sc[1]), fmaxf(sc[2], sc[3]));
#pragma unroll
                for (int off = 16; off > 0; off >>= 1)
                    rmax = fmaxf(rmax, __shfl_xor_sync(0xffffffffu, rmax, off));

                const float mnew = fmaxf(m[i], rmax);
                f[i] = __expf(m[i] - mnew);
                float pv[4], psum = 0.f;
#pragma unroll
                for (int cc = 0; cc < 4; cc++) { pv[cc] = __expf(sc[cc] - mnew); psum += pv[cc]; }
#pragma unroll
                for (int off = 16; off > 0; off >>= 1)
                    psum += __shfl_xor_sync(0xffffffffu, psum, off);

                lsum[i] = lsum[i] * f[i] + psum;
                m[i] = mnew;
#pragma unroll
                for (int cc = 0; cc < 4; cc++)
                    ptw[(l + 32 * cc) * 4 + i] = pv[cc];
            }
            // rescale accumulators by row-paired factors
            {
                ull f01 = pack2(f[0], f[1]);
                ull f23 = pack2(f[2], f[3]);
                fmul2(acc01[0], f01); fmul2(acc01[1], f01);
                fmul2(acc23[0], f23); fmul2(acc23[1], f23);
            }
            __syncwarp();

            // ---- P @ V : rows packed in pairs; P via 16B broadcast ----
#pragma unroll 4
            for (int j = 0; j < 128; j++) {
                ull p01, p23;
                lds_2x64(p01, p23, &ptw[j * 4]);     // broadcast: {p0,p1},{p2,p3}
                const float v0 = Vb[j * 64 + l];
                const float v1 = Vb[j * 64 + l + 32];
                const ull vv0 = pack2(v0, v0);
                const ull vv1 = pack2(v1, v1);
                ffma2(acc01[0], p01, vv0);
                ffma2(acc23[0], p23, vv0);
                ffma2(acc01[1], p01, vv1);
                ffma2(acc23[1], p23, vv1);
            }
            __syncthreads();   // all warps done with buf before it is refilled
        }

        // ---- epilogue ----
        float o01a, o01b, o23a, o23b;
        float inv0 = 1.0f / lsum[0], inv1 = 1.0f / lsum[1];
        float inv2 = 1.0f / lsum[2], inv3 = 1.0f / lsum[3];
        unpack2(acc01[0], o01a, o01b);
        unpack2(acc23[0], o23a, o23b);
        ob[(qs + (w << 2) + 0) * HH + l] = o01a * inv0;
        ob[(qs + (w << 2) + 1) * HH + l] = o01b * inv1;
        ob[(qs + (w << 2) + 2) * HH + l] = o23a * inv2;
        ob[(qs + (w << 2) + 3) * HH + l] = o23b * inv3;
        unpack2(acc01[1], o01a, o01b);
        unpack2(acc23[1], o23a, o23b);
        ob[(qs + (w << 2) + 0) * HH + l + 32] = o01a * inv0;
        ob[(qs + (w << 2) + 1) * HH + l + 32] = o01b * inv1;
        ob[(qs + (w << 2) + 2) * HH + l + 32] = o23a * inv2;
        ob[(qs + (w << 2) + 3) * HH + l + 32] = o23b * inv3;
    }
}

// ---------------------------------------------------------------------------
extern "C" void kernel_launch(void* const* d_in, const int* in_sizes, int n_in,
                              void* d_out, int out_size)
{
    const float* x  = (const float*)d_in[0];
    const float* Wq = (const float*)d_in[1];
    const float* Wk = (const float*)d_in[2];
    const float* Wv = (const float*)d_in[3];
    float* out = (float*)d_out;

    static int smem_set = 0;
    if (!smem_set) {
        cudaFuncSetAttribute(attn_kernel,
                             cudaFuncAttributeMaxDynamicSharedMemorySize,
                             ATTN_SMEM_BYTES);
        smem_set = 1;
    }

    proj_kernel<<<dim3(NROWS / 128, 3), 128>>>(x, Wq, Wk, Wv);
    attn_kernel<<<dim3(32, BB), 256, ATTN_SMEM_BYTES>>>(out);
}

// round 4
// speedup vs baseline: 1.2293x; 1.2293x over previous
#include <cuda_runtime.h>
#include <math.h>
#include <stdint.h>

#define BB 4
#define TT 2048
#define CC 1024
#define HH 64
#define NROWS (BB * TT)   // 8192

__device__ float g_q[NROWS * HH];
__device__ float g_k[NROWS * HH];
__device__ float g_v[NROWS * HH];

typedef unsigned long long ull;

// ---------------- f32x2 helpers ----------------
__device__ __forceinline__ void ffma2(ull& d, ull a, ull b) {
    asm("fma.rn.f32x2 %0, %1, %2, %0;" : "+l"(d) : "l"(a), "l"(b));
}
__device__ __forceinline__ void fmul2(ull& d, ull a) {
    asm("mul.rn.f32x2 %0, %0, %1;" : "+l"(d) : "l"(a));
}
__device__ __forceinline__ ull pack2(float lo, float hi) {
    ull r; asm("mov.b64 %0, {%1, %2};" : "=l"(r) : "f"(lo), "f"(hi)); return r;
}
__device__ __forceinline__ void unpack2(ull v, float& a, float& b) {
    asm("mov.b64 {%0, %1}, %2;" : "=f"(a), "=f"(b) : "l"(v));
}
__device__ __forceinline__ void lds_2x64(ull& a, ull& b, const void* p) {
    uint32_t sa = (uint32_t)__cvta_generic_to_shared(p);
    asm volatile("ld.shared.v2.u64 {%0, %1}, [%2];" : "=l"(a), "=l"(b) : "r"(sa));
}
__device__ __forceinline__ void cp_async16(void* smem_dst, const void* gptr) {
    uint32_t sa = (uint32_t)__cvta_generic_to_shared(smem_dst);
    asm volatile("cp.async.cg.shared.global [%0], [%1], 16;" :: "r"(sa), "l"(gptr));
}
#define CP_COMMIT() asm volatile("cp.async.commit_group;")
#define CP_WAIT(n)  asm volatile("cp.async.wait_group %0;" :: "n"(n))

// ---------------------------------------------------------------------------
// Kernel 1: QKV projection, f32x2 with n-packed accumulators (no spills).
// Block 256 threads -> tile 64(m) x 64(n), BK=16. Thread tile 4m x 4n,
// acc = ull[4][2] (n-pairs). As[k][m] scalar-LDG filled (reg double-buffer),
// Bs[k][n] natural via cp.async (smem double-buffer). grid = (128, 3).
// ---------------------------------------------------------------------------
__global__ __launch_bounds__(256) void proj_kernel(
    const float* __restrict__ x,
    const float* __restrict__ Wq,
    const float* __restrict__ Wk,
    const float* __restrict__ Wv)
{
    const float* W = (blockIdx.y == 0) ? Wq : (blockIdx.y == 1) ? Wk : Wv;
    float* out     = (blockIdx.y == 0) ? g_q : (blockIdx.y == 1) ? g_k : g_v;

    __shared__ float As[2][16][68];   // [buf][k][m], padded row
    __shared__ float Bs[2][16][64];   // [buf][k][n], natural

    const int tid  = threadIdx.x;
    const int tm   = tid >> 4;        // 0..15  -> m0 = tm*4
    const int tn   = tid & 15;        // 0..15  -> n0 = tn*4
    const int row0 = blockIdx.x * 64;

    // A fill lanes: k = lak, rows lam + 16*i (i<4)
    const int lak = tid & 15;
    const int lam = tid >> 4;
    // B fill lanes: one 16B chunk each
    const int bk = tid >> 4;          // 0..15
    const int bc = tid & 15;          // 0..15

    ull acc[4][2] = {};

    float ar[4];
    // prologue: stage 0
#pragma unroll
    for (int i = 0; i < 4; i++)
        ar[i] = x[(row0 + lam + 16 * i) * CC + lak];
    cp_async16(&Bs[0][bk][bc * 4], &W[bk * HH + bc * 4]);
    CP_COMMIT();
#pragma unroll
    for (int i = 0; i < 4; i++)
        As[0][lak][lam + 16 * i] = ar[i];

    for (int kt = 0; kt < 64; kt++) {
        const int buf = kt & 1;
        if (kt + 1 < 64) {
            const int k0n = (kt + 1) * 16;
#pragma unroll
            for (int i = 0; i < 4; i++)
                ar[i] = x[(row0 + lam + 16 * i) * CC + k0n + lak];
            cp_async16(&Bs[buf ^ 1][bk][bc * 4], &W[(k0n + bk) * HH + bc * 4]);
            CP_COMMIT();
            CP_WAIT(1);
        } else {
            CP_WAIT(0);
        }
        __syncthreads();   // A STS (this tile) + B cp.async (this tile) visible

#pragma unroll
        for (int k = 0; k < 16; k++) {
            float4 a4 = *(const float4*)&As[buf][k][tm * 4];
            ull b0, b1;
            lds_2x64(b0, b1, &Bs[buf][k][tn * 4]);
            ull a0 = pack2(a4.x, a4.x);
            ull a1 = pack2(a4.y, a4.y);
            ull a2p = pack2(a4.z, a4.z);
            ull a3 = pack2(a4.w, a4.w);
            ffma2(acc[0][0], a0, b0);  ffma2(acc[0][1], a0, b1);
            ffma2(acc[1][0], a1, b0);  ffma2(acc[1][1], a1, b1);
            ffma2(acc[2][0], a2p, b0); ffma2(acc[2][1], a2p, b1);
            ffma2(acc[3][0], a3, b0);  ffma2(acc[3][1], a3, b1);
        }

        if (kt + 1 < 64) {
            __syncthreads();   // everyone done reading buf^1 (used at kt-1)
#pragma unroll
            for (int i = 0; i < 4; i++)
                As[buf ^ 1][lak][lam + 16 * i] = ar[i];
        }
    }

#pragma unroll
    for (int r = 0; r < 4; r++) {
        float o0, o1, o2, o3;
        unpack2(acc[r][0], o0, o1);
        unpack2(acc[r][1], o2, o3);
        *(float4*)&out[(row0 + tm * 4 + r) * HH + tn * 4] =
            make_float4(o0, o1, o2, o3);
    }
}

// ---------------------------------------------------------------------------
// Kernel 2: causal attention, f32x2, 2 blocks/SM.
// Block 128 threads (4 warps), QT=16 query rows per phase.
// Phases: q-tile p then 127-p (128 tiles of 16 rows) -> balanced work.
// Key tiles of 64, cp.async double-buffered.
// Warp w: rows 4w..4w+3. Lane l: cols/dims {l, l+32}.
// smem 72KB -> 2 blocks per SM. grid = (64, 4) = 256 blocks.
// ---------------------------------------------------------------------------
#define SM_K(buf)  (sm + (buf) * 4096)            // 2 x 64 x 64
#define SM_V(buf)  (sm + 8192 + (buf) * 4096)
#define SM_Q       (sm + 16384)                   // 16 x 64
#define SM_PT      (sm + 17408)                   // 4 warps x 64 x 4
#define ATTN_SMEM_BYTES ((17408 + 1024) * 4)      // 73728 B = 72KB

__global__ __launch_bounds__(128) void attn_kernel(float* __restrict__ out)
{
    extern __shared__ float sm[];

    const int b   = blockIdx.y;
    const int p   = blockIdx.x;       // 0..63
    const int tid = threadIdx.x;
    const int w   = tid >> 5;
    const int l   = tid & 31;

    const float* qb = g_q + b * TT * HH;
    const float* kb = g_k + b * TT * HH;
    const float* vb = g_v + b * TT * HH;
    float*       ob = out + b * TT * HH;

    float* ptw = SM_PT + (w << 8);    // [64][4]

    for (int phase = 0; phase < 2; phase++) {
        const int qt = phase ? (127 - p) : p;
        const int qs = qt * 16;

        __syncthreads();   // previous phase fully done with all smem

        for (int idx = tid; idx < 16 * 64; idx += 128)
            SM_Q[idx] = qb[qs * 64 + idx];

        float m[4], lsum[4];
        ull acc01[2] = {0ull, 0ull};  // rows {0,1} packed; dims l, l+32
        ull acc23[2] = {0ull, 0ull};  // rows {2,3}
#pragma unroll
        for (int i = 0; i < 4; i++) { m[i] = -INFINITY; lsum[i] = 0.f; }

        const int nkb = (qs + 16 + 63) >> 6;

        // prologue: K/V tile 0 -> buf 0  (64x16 = 1024 chunks / 128 thr = 8 ea)
#pragma unroll
        for (int s = 0; s < 8; s++) {
            const int chunk = s * 128 + tid;
            const int row = chunk >> 4, c4 = chunk & 15;
            cp_async16(SM_K(0) + row * 64 + ((c4 ^ (row & 7)) << 2),
                       &kb[row * 64 + c4 * 4]);
        }
#pragma unroll
        for (int s = 0; s < 8; s++) {
            const int chunk = s * 128 + tid;
            const int row = chunk >> 4, c4 = chunk & 15;
            cp_async16(SM_V(0) + row * 64 + c4 * 4, &vb[row * 64 + c4 * 4]);
        }
        CP_COMMIT();

        for (int t = 0; t < nkb; t++) {
            const int buf = t & 1;
            if (t + 1 < nkb) {
                const float* kt_ = &kb[(t + 1) * 64 * 64];
                const float* vt_ = &vb[(t + 1) * 64 * 64];
#pragma unroll
                for (int s = 0; s < 8; s++) {
                    const int chunk = s * 128 + tid;
                    const int row = chunk >> 4, c4 = chunk & 15;
                    cp_async16(SM_K(buf ^ 1) + row * 64 + ((c4 ^ (row & 7)) << 2),
                               kt_ + row * 64 + c4 * 4);
                }
#pragma unroll
                for (int s = 0; s < 8; s++) {
                    const int chunk = s * 128 + tid;
                    const int row = chunk >> 4, c4 = chunk & 15;
                    cp_async16(SM_V(buf ^ 1) + row * 64 + c4 * 4,
                               vt_ + row * 64 + c4 * 4);
                }
                CP_COMMIT();
                CP_WAIT(1);
            } else {
                CP_WAIT(0);
            }
            __syncthreads();

            const float* Ks = SM_K(buf);
            const float* Vb = SM_V(buf);

            // ---- scores: k-packed f32x2, lane cols {l, l+32} ----
            ull s2[4][2] = {};
#pragma unroll
            for (int c4 = 0; c4 < 16; c4++) {
                ull k2a[2], k2b[2];
                lds_2x64(k2a[0], k2a[1], &Ks[l * 64 + ((c4 ^ (l & 7)) << 2)]);
                lds_2x64(k2b[0], k2b[1], &Ks[(l + 32) * 64 + ((c4 ^ (l & 7)) << 2)]);
                ull q2[2];
#pragma unroll
                for (int i = 0; i < 4; i++) {
                    lds_2x64(q2[0], q2[1], &SM_Q[((w << 2) + i) * 64 + c4 * 4]);
                    ffma2(s2[i][0], q2[0], k2a[0]);
                    ffma2(s2[i][0], q2[1], k2a[1]);
                    ffma2(s2[i][1], q2[0], k2b[0]);
                    ffma2(s2[i][1], q2[1], k2b[1]);
                }
            }

            // ---- online softmax, exact reference mask semantics ----
            float f[4];
#pragma unroll
            for (int i = 0; i < 4; i++) {
                const int rowg = qs + (w << 2) + i;
                float sc[2];
#pragma unroll
                for (int cc = 0; cc < 2; cc++) {
                    float lo, hi; unpack2(s2[i][cc], lo, hi);
                    float s = (lo + hi) * 0.125f;
                    const int col = t * 64 + l + 32 * cc;
                    if (col > rowg || s == 0.0f) s = -INFINITY;
                    sc[cc] = s;
                }
                float rmax = fmaxf(sc[0], sc[1]);
#pragma unroll
                for (int off = 16; off > 0; off >>= 1)
                    rmax = fmaxf(rmax, __shfl_xor_sync(0xffffffffu, rmax, off));

                const float mnew = fmaxf(m[i], rmax);
                f[i] = __expf(m[i] - mnew);
                const float p0 = __expf(sc[0] - mnew);
                const float p1 = __expf(sc[1] - mnew);

                float psum = p0 + p1;
#pragma unroll
                for (int off = 16; off > 0; off >>= 1)
                    psum += __shfl_xor_sync(0xffffffffu, psum, off);

                lsum[i] = lsum[i] * f[i] + psum;
                m[i] = mnew;
                ptw[l * 4 + i]        = p0;
                ptw[(l + 32) * 4 + i] = p1;
            }
            {
                ull f01 = pack2(f[0], f[1]);
                ull f23 = pack2(f[2], f[3]);
                fmul2(acc01[0], f01); fmul2(acc01[1], f01);
                fmul2(acc23[0], f23); fmul2(acc23[1], f23);
            }
            __syncwarp();

            // ---- P @ V : rows packed; P via 16B warp-broadcast ----
#pragma unroll 4
            for (int j = 0; j < 64; j++) {
                ull p01, p23;
                lds_2x64(p01, p23, &ptw[j * 4]);
                const float v0 = Vb[j * 64 + l];
                const float v1 = Vb[j * 64 + l + 32];
                const ull vv0 = pack2(v0, v0);
                const ull vv1 = pack2(v1, v1);
                ffma2(acc01[0], p01, vv0);
                ffma2(acc23[0], p23, vv0);
                ffma2(acc01[1], p01, vv1);
                ffma2(acc23[1], p23, vv1);
            }
            __syncthreads();   // all warps done with buf before refill
        }

        // ---- epilogue ----
        float oa, obv;
        const float inv0 = 1.0f / lsum[0], inv1 = 1.0f / lsum[1];
        const float inv2 = 1.0f / lsum[2], inv3 = 1.0f / lsum[3];
        unpack2(acc01[0], oa, obv);
        ob[(qs + (w << 2) + 0) * HH + l] = oa * inv0;
        ob[(qs + (w << 2) + 1) * HH + l] = obv * inv1;
        unpack2(acc23[0], oa, obv);
        ob[(qs + (w << 2) + 2) * HH + l] = oa * inv2;
        ob[(qs + (w << 2) + 3) * HH + l] = obv * inv3;
        unpack2(acc01[1], oa, obv);
        ob[(qs + (w << 2) + 0) * HH + l + 32] = oa * inv0;
        ob[(qs + (w << 2) + 1) * HH + l + 32] = obv * inv1;
        unpack2(acc23[1], oa, obv);
        ob[(qs + (w << 2) + 2) * HH + l + 32] = oa * inv2;
        ob[(qs + (w << 2) + 3) * HH + l + 32] = obv * inv3;
    }
}

// ---------------------------------------------------------------------------
extern "C" void kernel_launch(void* const* d_in, const int* in_sizes, int n_in,
                              void* d_out, int out_size)
{
    const float* x  = (const float*)d_in[0];
    const float* Wq = (const float*)d_in[1];
    const float* Wk = (const float*)d_in[2];
    const float* Wv = (const float*)d_in[3];
    float* out = (float*)d_out;

    static int smem_set = 0;
    if (!smem_set) {
        cudaFuncSetAttribute(attn_kernel,
                             cudaFuncAttributeMaxDynamicSharedMemorySize,
                             ATTN_SMEM_BYTES);
        smem_set = 1;
    }

    proj_kernel<<<dim3(NROWS / 64, 3), 256>>>(x, Wq, Wk, Wv);
    attn_kernel<<<dim3(64, BB), 128, ATTN_SMEM_BYTES>>>(out);
}